// round 11
// baseline (speedup 1.0000x reference)
#include <cuda_runtime.h>
#include <cstdint>

// Problem constants
#define BQ   2
#define NQ   6
#define CQ   3
#define HQ   64
#define WQ   176
#define DQ   64
#define HWQ  (HQ * WQ)        // 11264
#define BN   (BQ * NQ)        // 12
#define ROWS (BN * CQ)        // 36
#define CHUNKS 8              // partial-sum chunks per row
#define F4_PER_CHUNK ((HWQ / 4) / CHUNKS)   // 352

#define TILE_PX 32
#define TILE_F4 (3 * TILE_PX * (DQ / 4))    // 1536 float4 = 24 KB

// Scratch (no device allocs allowed)
__device__ float g_partial[ROWS][CHUNKS];
__device__ float g_kinv[BN][9];

// ---------------------------------------------------------------------------
// Kernel 1 (producer): partial sum of exp per (row, chunk) + intrinsics K^{-1}.
// grid=(CHUNKS, ROWS)=288 blocks, 128 threads. Signals PDL dependents early.
// ---------------------------------------------------------------------------
__global__ __launch_bounds__(128) void lss_stats_kernel(
    const float* __restrict__ feat,      // (BN, C, HW)
    const float* __restrict__ intr)      // (B, N, 4, 4)
{
    if (threadIdx.x == 0)
        asm volatile("griddepcontrol.launch_dependents;" ::: "memory");

    const int chunk = blockIdx.x;        // 0..7
    const int row   = blockIdx.y;        // 0..35
    const int tid   = threadIdx.x;

    if (chunk == 0 && (row % CQ) == 0 && tid == 0) {
        const int bn = row / CQ;
        const float* A = intr + bn * 16;
        float a = A[0], b = A[1], c = A[2];
        float d = A[4], e = A[5], f = A[6];
        float g = A[8], h = A[9], i = A[10];
        float det = a * (e * i - f * h) - b * (d * i - f * g) + c * (d * h - e * g);
        float id  = 1.0f / det;
        float* kv = g_kinv[bn];
        kv[0] = (e * i - f * h) * id;  kv[1] = (c * h - b * i) * id;  kv[2] = (b * f - c * e) * id;
        kv[3] = (f * g - d * i) * id;  kv[4] = (a * i - c * g) * id;  kv[5] = (c * d - a * f) * id;
        kv[6] = (d * h - e * g) * id;  kv[7] = (b * g - a * h) * id;  kv[8] = (a * e - b * d) * id;
    }

    const float4* f4 = reinterpret_cast<const float4*>(feat + (size_t)row * HWQ)
                       + chunk * F4_PER_CHUNK;
    float sum = 0.0f;
    for (int idx = tid; idx < F4_PER_CHUNK; idx += 128) {
        float4 v = f4[idx];
        sum += __expf(v.x) + __expf(v.y) + __expf(v.z) + __expf(v.w);
    }
    #pragma unroll
    for (int o = 16; o > 0; o >>= 1) sum += __shfl_xor_sync(0xFFFFFFFFu, sum, o);

    __shared__ float sw[4];
    if ((tid & 31) == 0) sw[tid >> 5] = sum;
    __syncthreads();
    if (tid == 0)
        g_partial[row][chunk] = sw[0] + sw[1] + sw[2] + sw[3];
}

// ---------------------------------------------------------------------------
// Kernel 2 (consumer, PDL): 32 pixels/block, 4224 blocks. Output tile is
// built in SMEM (STS only) and drained by TMA bulk stores — no per-thread
// STG on the critical path.
// ---------------------------------------------------------------------------
__global__ __launch_bounds__(256) void lss_main_kernel(
    const float* __restrict__ feat,      // (BN, C, HW)
    const float* __restrict__ extr,      // (B, N, 4, 4)
    const float* __restrict__ depths,    // (D)
    float* __restrict__ out)             // (BN, 3, HW, D)
{
    const int bn  = blockIdx.y;
    const int tid = threadIdx.x;
    const int p0  = blockIdx.x * TILE_PX;

    extern __shared__ float4 sbuf[];     // [3][TILE_PX][16] = 24 KB
    __shared__ float sS[3][TILE_PX];
    __shared__ float sE[12];
    __shared__ float sInv[3];

    // ---- Independent preamble (no stats dependency) ----
    float e0 = 0.f, e1 = 0.f, e2 = 0.f, x = 0.f, y = 0.f;
    if (tid < TILE_PX) {
        const int p = p0 + tid;
        x = (float)(p % WQ);
        y = (float)(p / WQ);
        const size_t fbase = (size_t)bn * CQ * HWQ + p;
        e0 = __expf(feat[fbase          ]);
        e1 = __expf(feat[fbase +     HWQ]);
        e2 = __expf(feat[fbase + 2 * HWQ]);
    }
    if (tid < 12) sE[tid] = extr[bn * 16 + tid];

    const int q   = tid & 15;            // depth-quad index, fixed per thread
    const int idx = tid >> 4;            // 0..15
    const float4 dep = reinterpret_cast<const float4*>(depths)[q];

    // ---- Wait for stats results ----
    asm volatile("griddepcontrol.wait;" ::: "memory");

    if (tid < 24) {
        const int r = tid >> 3, ch = tid & 7;
        float v = g_partial[bn * CQ + r][ch];
        v += __shfl_xor_sync(0x00FFFFFFu, v, 4);
        v += __shfl_xor_sync(0x00FFFFFFu, v, 2);
        v += __shfl_xor_sync(0x00FFFFFFu, v, 1);
        if (ch == 0) sInv[r] = 1.0f / v;
    }
    __syncthreads();

    if (tid < TILE_PX) {
        const float* kv = g_kinv[bn];
        const float t0 = e0 * sInv[0] * fmaf(kv[0], x, fmaf(kv[1], y, kv[2]));
        const float t1 = e1 * sInv[1] * fmaf(kv[3], x, fmaf(kv[4], y, kv[5]));
        const float t2 = e2 * sInv[2] * fmaf(kv[6], x, fmaf(kv[7], y, kv[8]));
        #pragma unroll
        for (int i = 0; i < 3; i++)
            sS[i][tid] = fmaf(sE[i * 4 + 0], t0,
                         fmaf(sE[i * 4 + 1], t1,
                              sE[i * 4 + 2] * t2));
    }
    __syncthreads();

    // ---- Build the 24 KB tile in SMEM (6 float4 STS per thread) ----
    #pragma unroll
    for (int i = 0; i < 3; i++) {
        const float e3 = sE[i * 4 + 3];
        #pragma unroll
        for (int r = 0; r < 2; r++) {
            const int pl = r * 16 + idx;
            const float s = sS[i][pl];
            float4 o;
            o.x = fmaf(s, dep.x, e3);
            o.y = fmaf(s, dep.y, e3);
            o.z = fmaf(s, dep.z, e3);
            o.w = fmaf(s, dep.w, e3);
            sbuf[(i * TILE_PX + pl) * 16 + q] = o;
        }
    }
    __syncthreads();

    // ---- Drain via TMA bulk stores: 3 x 8 KB contiguous spans ----
    if (tid == 0) {
        asm volatile("fence.proxy.async.shared::cta;" ::: "memory");
        uint32_t sm;
        asm("{ .reg .u64 t; cvta.to.shared.u64 t, %1; cvt.u32.u64 %0, t; }"
            : "=r"(sm) : "l"(sbuf));
        #pragma unroll
        for (int i = 0; i < 3; i++) {
            const float* dst = out + ((size_t)(bn * 3 + i) * HWQ + p0) * DQ;
            asm volatile(
                "cp.async.bulk.global.shared::cta.bulk_group [%0], [%1], %2;"
                :: "l"(dst), "r"(sm + i * TILE_PX * 256), "n"(TILE_PX * 256)
                : "memory");
        }
        asm volatile("cp.async.bulk.commit_group;" ::: "memory");
        // Wait until TMA has finished READING smem, so CTA exit is safe.
        asm volatile("cp.async.bulk.wait_group.read 0;" ::: "memory");
    }
}

extern "C" void kernel_launch(void* const* d_in, const int* in_sizes, int n_in,
                              void* d_out, int out_size)
{
    const float* feat   = (const float*)d_in[0];  // image_features (BN,C,H,W)
    const float* intr   = (const float*)d_in[1];  // intrinsics (B,N,4,4)
    const float* extr   = (const float*)d_in[2];  // extrinsics (B,N,4,4)
    // d_in[3] = xy1 (unused)
    const float* depths = (const float*)d_in[4];  // (D)
    float* out = (float*)d_out;

    static int smem_set = 0;
    if (!smem_set) {
        cudaFuncSetAttribute(lss_main_kernel,
                             cudaFuncAttributeMaxDynamicSharedMemorySize,
                             TILE_F4 * 16);
        smem_set = 1;
    }

    dim3 sgrid(CHUNKS, ROWS);
    lss_stats_kernel<<<sgrid, 128>>>(feat, intr);

    cudaLaunchConfig_t cfg = {};
    cfg.gridDim  = dim3(HWQ / TILE_PX, BN);
    cfg.blockDim = dim3(256, 1, 1);
    cfg.dynamicSmemBytes = TILE_F4 * 16;   // 24 KB
    cfg.stream = 0;
    cudaLaunchAttribute attr[1];
    attr[0].id = cudaLaunchAttributeProgrammaticStreamSerialization;
    attr[0].val.programmaticStreamSerializationAllowed = 1;
    cfg.attrs = attr;
    cfg.numAttrs = 1;
    cudaLaunchKernelEx(&cfg, lss_main_kernel, feat, extr, depths, out);
}